// round 4
// baseline (speedup 1.0000x reference)
#include <cuda_runtime.h>
#include <cuda_bf16.h>

#define MAXN 50176
#define MAXE 850176

// -------- scratch (device globals; no allocation allowed) --------
__device__ float  g_xl[MAXN * 64];      // lin(x)  [N,64]
__device__ float  g_si[MAXN];           // per-node dst-side logit
__device__ float  g_sj[MAXN];           // per-node src-side logit
__device__ int    g_deg[MAXN];          // in-degree (incl. self loop)
__device__ int    g_rowptr[MAXN + 1];
__device__ int    g_rank[MAXE];         // per-edge rank within dst (1..deg)
__device__ int    g_csrc[MAXE + MAXN];  // CSR src ids (dst-sorted)
__device__ double g_bnsum[128];         // [0:64) sum, [64:128) sumsq

// -------- K1: xl = x @ W^T, per-node attention scalars, + init duties --------
__global__ void k_gemm(const float* __restrict__ x, const float* __restrict__ W,
                       const float* __restrict__ emb,
                       const float* __restrict__ att_i, const float* __restrict__ att_j,
                       const float* __restrict__ att_em_i, const float* __restrict__ att_em_j,
                       int N) {
    __shared__ float2 Wt2[64][32];      // Wt2[k][l] = (W[2l][k], W[2l+1][k])
    int tid = threadIdx.x;
    if (blockIdx.x == 0 && tid < 128) g_bnsum[tid] = 0.0;   // fused init
    for (int s = tid; s < 64 * 32; s += 256) {
        int k = s >> 5, l = s & 31;
        Wt2[k][l] = make_float2(W[(2 * l) * 64 + k], W[(2 * l + 1) * 64 + k]);
    }
    __syncthreads();
    int warp = tid >> 5, lane = tid & 31;
    int c0 = 2 * lane;
    float ai0 = att_i[c0],    ai1 = att_i[c0 + 1];
    float aj0 = att_j[c0],    aj1 = att_j[c0 + 1];
    float e0i = att_em_i[c0], e1i = att_em_i[c0 + 1];
    float e0j = att_em_j[c0], e1j = att_em_j[c0 + 1];

    for (int r = blockIdx.x * 8 + warp; r < N; r += gridDim.x * 8) {
        float xv0 = x[r * 64 + lane];
        float xv1 = x[r * 64 + 32 + lane];
        float a0 = 0.f, a1 = 0.f;
#pragma unroll
        for (int k = 0; k < 32; k++) {
            float xk = __shfl_sync(0xffffffffu, xv0, k);
            float2 w = Wt2[k][lane];
            a0 = fmaf(xk, w.x, a0);
            a1 = fmaf(xk, w.y, a1);
        }
#pragma unroll
        for (int k = 0; k < 32; k++) {
            float xk = __shfl_sync(0xffffffffu, xv1, k);
            float2 w = Wt2[32 + k][lane];
            a0 = fmaf(xk, w.x, a0);
            a1 = fmaf(xk, w.y, a1);
        }
        *(float2*)&g_xl[r * 64 + c0] = make_float2(a0, a1);

        float2 em = *(const float2*)&emb[r * 64 + c0];
        float si = a0 * ai0 + a1 * ai1 + em.x * e0i + em.y * e1i;
        float sj = a0 * aj0 + a1 * aj1 + em.x * e0j + em.y * e1j;
#pragma unroll
        for (int o = 16; o; o >>= 1) {
            si += __shfl_xor_sync(0xffffffffu, si, o);
            sj += __shfl_xor_sync(0xffffffffu, sj, o);
        }
        if (lane == 0) { g_si[r] = si; g_sj[r] = sj; g_deg[r] = 1; }  // fused deg init
    }
}

// -------- K2: degree count + per-edge rank (the only atomic pass) --------
__global__ void k_count(const int* __restrict__ ei, int E) {
    int t = blockIdx.x * blockDim.x + threadIdx.x;
    int E4 = E >> 2;
    if (t < E4) {
        int4 d4 = *(const int4*)&ei[E + 4 * t];
        int4 r4;
        r4.x = atomicAdd(&g_deg[d4.x], 1);
        r4.y = atomicAdd(&g_deg[d4.y], 1);
        r4.z = atomicAdd(&g_deg[d4.z], 1);
        r4.w = atomicAdd(&g_deg[d4.w], 1);
        *(int4*)&g_rank[4 * t] = r4;
    } else {
        int e = 4 * E4 + (t - E4);
        if (e < E) g_rank[e] = atomicAdd(&g_deg[ei[E + e]], 1);
    }
}

// -------- K3: exclusive scan (single block, smem-staged) + self-loop emit --------
__global__ void k_scan(int N) {
    extern __shared__ int sdeg[];                 // N ints (~200 KB)
    __shared__ int wtot[32];
    __shared__ int s_total;
    int tid = threadIdx.x, lane = tid & 31, wid = tid >> 5;

    for (int i = tid; i < N; i += 1024) sdeg[i] = g_deg[i];
    __syncthreads();

    int chunk = (N + 1023) >> 10;
    int beg = tid * chunk;
    int end = beg + chunk; if (end > N) end = N;
    int sum = 0;
    for (int i = beg; i < end; i++) sum += sdeg[i];

    int incl = sum;
#pragma unroll
    for (int d = 1; d < 32; d <<= 1) {
        int t = __shfl_up_sync(0xffffffffu, incl, d);
        if (lane >= d) incl += t;
    }
    if (lane == 31) wtot[wid] = incl;
    __syncthreads();
    if (wid == 0) {
        int s = wtot[lane];
        int si_ = s;
#pragma unroll
        for (int d = 1; d < 32; d <<= 1) {
            int t = __shfl_up_sync(0xffffffffu, si_, d);
            if (lane >= d) si_ += t;
        }
        wtot[lane] = si_ - s;
        if (lane == 31) s_total = si_;
    }
    __syncthreads();
    int excl = wtot[wid] + incl - sum;

    for (int i = beg; i < end; i++) { int v = sdeg[i]; sdeg[i] = excl; excl += v; }
    __syncthreads();

    for (int i = tid; i < N; i += 1024) {
        int p = sdeg[i];
        g_rowptr[i] = p;
        g_csrc[p] = i;                            // self-loop at rank 0
    }
    if (tid == 0) g_rowptr[N] = s_total;
}

// -------- K4: atomic-free scatter via precomputed ranks --------
__global__ void k_scatter(const int* __restrict__ ei, int E) {
    int e = blockIdx.x * blockDim.x + threadIdx.x;
    if (e >= E) return;
    int s = ei[e];
    int d = ei[E + e];
    g_csrc[g_rowptr[d] + g_rank[e]] = s;
}

// -------- K5: softmax agg (lane-parallel exp, broadcast gather) + fused BN stats --------
__global__ void k_agg(const float* __restrict__ bias, float* __restrict__ out, int N) {
    __shared__ double sred[128];
    int tid = threadIdx.x, warp = tid >> 5, lane = tid & 31;
    if (tid < 128) sred[tid] = 0.0;
    __syncthreads();

    int c0 = 2 * lane;
    float2 b2 = *(const float2*)&bias[c0];
    double p0 = 0.0, p1 = 0.0, q0 = 0.0, q1 = 0.0;   // BN partials for ch c0, c0+1

    for (int i = blockIdx.x * 8 + warp; i < N; i += gridDim.x * 8) {
        int beg = g_rowptr[i], end = g_rowptr[i + 1];
        float si = g_si[i];
        float ssum = 0.f, ax = 0.f, ay = 0.f;

        for (int base = beg; base < end; base += 32) {
            int k = base + lane;
            int s = 0; float w = 0.f;
            if (k < end) {
                s = g_csrc[k];
                float a = si + g_sj[s];
                a = a >= 0.f ? a : 0.2f * a;
                w = __expf(a);                        // lane-parallel: 1 MUFU / 32 edges
            }
            float wsum = w;
#pragma unroll
            for (int o = 16; o; o >>= 1) wsum += __shfl_xor_sync(0xffffffffu, wsum, o);
            ssum += wsum;

            int cnt = end - base; if (cnt > 32) cnt = 32;
            for (int k2 = 0; k2 < cnt; k2++) {        // independent gathers, full MLP
                float wk = __shfl_sync(0xffffffffu, w, k2);
                int   sk = __shfl_sync(0xffffffffu, s, k2);
                float2 v = *(const float2*)&g_xl[sk * 64 + c0];
                ax = fmaf(wk, v.x, ax);
                ay = fmaf(wk, v.y, ay);
            }
        }
        float inv = 1.f / (ssum + 1e-16f);
        float ox = fmaf(ax, inv, b2.x);
        float oy = fmaf(ay, inv, b2.y);
        *(float2*)&out[i * 64 + c0] = make_float2(ox, oy);
        p0 += (double)ox; q0 += (double)ox * ox;
        p1 += (double)oy; q1 += (double)oy * oy;
    }

    // block-level BN reduction: 8 warps -> smem doubles -> 128 global atomics
    atomicAdd(&sred[c0],        p0);
    atomicAdd(&sred[c0 + 1],    p1);
    atomicAdd(&sred[64 + c0],   q0);
    atomicAdd(&sred[64 + c0 + 1], q1);
    __syncthreads();
    if (tid < 128) atomicAdd(&g_bnsum[tid], sred[tid]);
}

// -------- K6: apply BN + ReLU (finalize fused per-block) --------
__global__ void k_bnapply(const float* __restrict__ gamma, const float* __restrict__ beta,
                          float* __restrict__ out, int N) {
    __shared__ float s_scale[64], s_shift[64];
    int tid = threadIdx.x;
    if (tid < 64) {
        double mu  = g_bnsum[tid] / (double)N;
        double var = g_bnsum[64 + tid] / (double)N - mu * mu;
        float sc = (float)(rsqrt(var + 1e-5)) * gamma[tid];
        s_scale[tid] = sc;
        s_shift[tid] = fmaf(-(float)mu, sc, beta[tid]);
    }
    __syncthreads();
    int idx = blockIdx.x * blockDim.x + tid;
    if (idx >= N * 64) return;
    int c = idx & 63;
    float v = fmaf(out[idx], s_scale[c], s_shift[c]);
    out[idx] = fmaxf(v, 0.f);
}

extern "C" void kernel_launch(void* const* d_in, const int* in_sizes, int n_in,
                              void* d_out, int out_size) {
    const float* x        = (const float*)d_in[0];
    const int*   ei       = (const int*)d_in[1];
    const float* emb      = (const float*)d_in[2];
    const float* W        = (const float*)d_in[3];
    const float* att_i    = (const float*)d_in[4];
    const float* att_j    = (const float*)d_in[5];
    const float* att_em_i = (const float*)d_in[6];
    const float* att_em_j = (const float*)d_in[7];
    const float* bias     = (const float*)d_in[8];
    const float* gamma    = (const float*)d_in[9];
    const float* beta     = (const float*)d_in[10];
    float* out = (float*)d_out;

    int N = in_sizes[0] / 64;
    int E = in_sizes[1] / 2;

    cudaFuncSetAttribute(k_scan, cudaFuncAttributeMaxDynamicSharedMemorySize, MAXN * 4);
    size_t scan_smem = (size_t)N * 4;

    int E4 = E >> 2;
    int cnt_threads = E4 + (E - 4 * E4);

    k_gemm<<<1480, 256>>>(x, W, emb, att_i, att_j, att_em_i, att_em_j, N);
    k_count<<<(cnt_threads + 255) / 256, 256>>>(ei, E);
    k_scan<<<1, 1024, scan_smem>>>(N);
    k_scatter<<<(E + 255) / 256, 256>>>(ei, E);
    k_agg<<<1184, 256>>>(bias, out, N);
    k_bnapply<<<(N * 64 + 255) / 256, 256>>>(gamma, beta, out, N);
}